// round 3
// baseline (speedup 1.0000x reference)
#include <cuda_runtime.h>
#include <math.h>

#define BATCH 2097152
#define HID 64
#define NB 8
#define NRAW 25           // 3*NB + 1
#define CAP 4352          // raw breakpoint capacity (>= 64 + 65*64 = 4224)
#define BPN 8192          // padded sorted breakpoint array (power of 2)
#define SEG_N (CAP + 1)   // 4353 segments
#define SEG_STRIDE 52     // 25 slopes + 25 intercepts + 2 pad (13 x float4)

// ---- scratch (static device globals; no allocation) ----
__device__ float g_theta_sorted[HID];
__device__ float g_bp_raw[CAP];
__device__ __align__(16) float g_bp_sorted[BPN];
__device__ int   g_rank[CAP];
__device__ int   g_bp_count;
__device__ __align__(16) float g_seg[(size_t)SEG_N * SEG_STRIDE];

__device__ __forceinline__ float seg_eval_point(float lo, float hi) {
    bool lf = isfinite(lo), hf = isfinite(hi);
    if (lf && hf) return 0.5f * (lo + hi);
    if (lf) return lo + 1.0f;   // tail segment (lo, +inf)
    if (hf) return hi - 1.0f;   // tail segment (-inf, hi)
    return 0.0f;                // unreachable padding segment
}

// K1: init scratch, compute & sort layer-1 thresholds, seed breakpoint list
__global__ void k_init(const float* __restrict__ W1, const float* __restrict__ b1) {
    int i = threadIdx.x; // 64 threads
    for (int p = i; p < BPN; p += HID) g_bp_sorted[p] = INFINITY;
    for (int p = i; p < CAP; p += HID) { g_bp_raw[p] = INFINITY; g_rank[p] = 0; }
    if (i == 0) g_bp_count = 0;

    __shared__ float sth[HID];
    float a = W1[i], b = b1[i];
    float th = -b / a;
    if (!isfinite(th)) th = INFINITY; // a==0: unit is constant; handled by midpoint masks
    sth[i] = th;
    __syncthreads();

    int r = 0;
    for (int x = 0; x < HID; x++) {
        float u = sth[x];
        r += (u < th) || (u == th && x < i);
    }
    g_theta_sorted[r] = th;
    if (isfinite(th)) {
        int id = atomicAdd(&g_bp_count, 1);
        if (id < CAP) g_bp_raw[id] = th;
    }
}

// K2: per layer-1 region, find layer-2 zero crossings, append as breakpoints
__global__ void k_cross(const float* __restrict__ W1, const float* __restrict__ b1,
                        const float* __restrict__ W2, const float* __restrict__ b2) {
    int r = blockIdx.x;  // 0..64
    int j = threadIdx.x; // 0..63
    float lo = (r == 0)   ? -INFINITY : g_theta_sorted[r - 1];
    float hi = (r == HID) ?  INFINITY : g_theta_sorted[r];
    float t = seg_eval_point(lo, hi);

    float A = 0.f, Bc = __ldg(b2 + j);
    #pragma unroll 4
    for (int i = 0; i < HID; i++) {
        float a = __ldg(W1 + i), b = __ldg(b1 + i);
        float w = __ldg(W2 + j * HID + i);
        if (fmaf(a, t, b) > 0.f) { A = fmaf(w, a, A); Bc = fmaf(w, b, Bc); }
    }
    float tc = -Bc / A;
    if (isfinite(tc) && tc > lo && tc < hi) {
        int id = atomicAdd(&g_bp_count, 1);
        if (id < CAP) g_bp_raw[id] = tc;
    }
}

// K3a: rank-by-counting (partial, 8 slices per element for parallelism)
__global__ void k_rank() {
    int idx = blockIdx.x * blockDim.x + threadIdx.x;
    if (idx >= CAP * 8) return;
    int g = idx >> 3, s = idx & 7;
    float v = g_bp_raw[g];
    int base = s * (CAP / 8);
    int part = 0;
    #pragma unroll 4
    for (int q = 0; q < CAP / 8; q++) {
        int x = base + q;
        float u = __ldg(g_bp_raw + x);
        part += ((u < v) || (u == v && x < g)) ? 1 : 0;
    }
    atomicAdd(&g_rank[g], part);
}

// K3b: scatter into sorted order
__global__ void k_scatter() {
    int g = blockIdx.x * blockDim.x + threadIdx.x;
    if (g < CAP) g_bp_sorted[g_rank[g]] = g_bp_raw[g];
}

// K4: per-segment exact affine coefficients of raw(t) (one warp per segment)
__global__ void k_segcoef(const float* __restrict__ W1, const float* __restrict__ b1,
                          const float* __restrict__ W2, const float* __restrict__ b2,
                          const float* __restrict__ W3, const float* __restrict__ b3) {
    __shared__ float sW2[HID * 65];   // padded stride 65: conflict-free per-j reads
    __shared__ float sW3[NRAW * HID];
    __shared__ float sa[HID], sb[HID];
    int tid = threadIdx.x;
    for (int p = tid; p < HID * HID; p += blockDim.x) {
        int j = p >> 6, i = p & 63;
        sW2[j * 65 + i] = W2[p];
    }
    for (int p = tid; p < NRAW * HID; p += blockDim.x) sW3[p] = W3[p];
    if (tid < HID) { sa[tid] = W1[tid]; sb[tid] = b1[tid]; }
    __syncthreads();

    int warp = tid >> 5, lane = tid & 31;
    int m = blockIdx.x * (blockDim.x >> 5) + warp;
    if (m >= SEG_N) return;

    float lo = (m == 0) ? -INFINITY : g_bp_sorted[m - 1];
    float hi = g_bp_sorted[m]; // m <= CAP < BPN; INF padding handles tails
    float tm = seg_eval_point(lo, hi);

    int j0 = lane, j1 = lane + 32;
    float A0 = 0.f, B0 = __ldg(b2 + j0);
    float A1 = 0.f, B1 = __ldg(b2 + j1);
    #pragma unroll 4
    for (int i = 0; i < HID; i++) {
        float a = sa[i], b = sb[i];
        float va = 0.f, vb = 0.f;
        if (fmaf(a, tm, b) > 0.f) { va = a; vb = b; }
        float w0 = sW2[j0 * 65 + i], w1 = sW2[j1 * 65 + i];
        A0 = fmaf(w0, va, A0); B0 = fmaf(w0, vb, B0);
        A1 = fmaf(w1, va, A1); B1 = fmaf(w1, vb, B1);
    }
    // layer-2 relu: sign constant inside a segment
    if (!(fmaf(A0, tm, B0) > 0.f)) { A0 = 0.f; B0 = 0.f; }
    if (!(fmaf(A1, tm, B1) > 0.f)) { A1 = 0.f; B1 = 0.f; }

    float* segp = g_seg + (size_t)m * SEG_STRIDE;
    #pragma unroll
    for (int k = 0; k < NRAW; k++) {
        float s = sW3[k * HID + j0] * A0 + sW3[k * HID + j1] * A1;
        float c = sW3[k * HID + j0] * B0 + sW3[k * HID + j1] * B1;
        #pragma unroll
        for (int o = 16; o > 0; o >>= 1) {
            s += __shfl_xor_sync(0xffffffffu, s, o);
            c += __shfl_xor_sync(0xffffffffu, c, o);
        }
        if (lane == 0) { segp[k] = s; segp[NRAW + k] = c + __ldg(b3 + k); }
    }
    if (lane == 0) { segp[50] = 0.f; segp[51] = 0.f; }
}

// K5: main per-row kernel: segment lookup + 25 FMAs + RQS spline
__global__ void __launch_bounds__(256) k_main(const float2* __restrict__ x,
                                              float* __restrict__ out) {
    __shared__ float sbp[BPN]; // 32 KB sorted breakpoints (INF padded)
    {
        float4* s4 = (float4*)sbp;
        const float4* g4 = (const float4*)g_bp_sorted;
        for (int p = threadIdx.x; p < BPN / 4; p += blockDim.x) s4[p] = g4[p];
    }
    __syncthreads();

    int i = blockIdx.x * blockDim.x + threadIdx.x;
    if (i >= BATCH) return;
    float2 xv = __ldg(x + i);
    float t = xv.x, u = xv.y;

    // p = #{bp < t}; fixed 13-step uniform binary search (INF padding => safe)
    int p = 0;
    #pragma unroll
    for (int s = BPN / 2; s >= 1; s >>= 1) {
        int q = p + s;
        if (sbp[q - 1] < t) p = q;
    }

    // load 52 floats of segment coefficients (13 x LDG.128, hot in L1/L2)
    const float4* seg4 = (const float4*)(g_seg + (size_t)p * SEG_STRIDE);
    float c[52];
    #pragma unroll
    for (int q = 0; q < 13; q++) {
        float4 v = __ldg(seg4 + q);
        c[4 * q] = v.x; c[4 * q + 1] = v.y; c[4 * q + 2] = v.z; c[4 * q + 3] = v.w;
    }
    float raw[NRAW];
    #pragma unroll
    for (int k = 0; k < NRAW; k++) raw[k] = fmaf(c[k], t, c[NRAW + k]);

    // softmax(widths)*10
    float wm = raw[0];
    #pragma unroll
    for (int k = 1; k < NB; k++) wm = fmaxf(wm, raw[k]);
    float ew[NB], sumw = 0.f;
    #pragma unroll
    for (int k = 0; k < NB; k++) { ew[k] = __expf(raw[k] - wm); sumw += ew[k]; }
    float scw = __fdividef(10.0f, sumw);

    // softmax(heights)*10
    float hm = raw[NB];
    #pragma unroll
    for (int k = 1; k < NB; k++) hm = fmaxf(hm, raw[NB + k]);
    float eh[NB], sumh = 0.f;
    #pragma unroll
    for (int k = 0; k < NB; k++) { eh[k] = __expf(raw[NB + k] - hm); sumh += eh[k]; }
    float sch = __fdividef(10.0f, sumh);

    // softplus(derivs) + 0.001
    float dv[NB + 1];
    #pragma unroll
    for (int k = 0; k < NB + 1; k++) {
        float z = raw[2 * NB + k];
        dv[k] = fmaxf(z, 0.f) + log1pf(__expf(-fabsf(z))) + 0.001f;
    }

    // knots (cumsum) and bin index
    float wv[NB], hv[NB], cwk[NB + 1], chk[NB + 1];
    cwk[0] = -5.f; chk[0] = -5.f;
    #pragma unroll
    for (int k = 0; k < NB; k++) {
        wv[k] = ew[k] * scw;
        hv[k] = eh[k] * sch;
        cwk[k + 1] = cwk[k] + wv[k];
        chk[k + 1] = chk[k] + hv[k];
    }
    int bin = 0;
    #pragma unroll
    for (int k = 1; k < NB; k++) bin += (cwk[k] < u) ? 1 : 0;

    // gather bin-indexed values via predicated selects
    float w_k = wv[0], h_k = hv[0], x_k = cwk[0], y_k = chk[0], d_k = dv[0], d_k1 = dv[1];
    #pragma unroll
    for (int k = 1; k < NB; k++) {
        bool pr = (bin >= k);
        w_k = pr ? wv[k] : w_k;
        h_k = pr ? hv[k] : h_k;
        x_k = pr ? cwk[k] : x_k;
        y_k = pr ? chk[k] : y_k;
        d_k = pr ? dv[k] : d_k;
        d_k1 = pr ? dv[k + 1] : d_k1;
    }

    float s_k = __fdividef(h_k, w_k);
    float xi = fminf(fmaxf(__fdividef(u - x_k, w_k), 0.f), 1.f);
    float om = 1.f - xi;
    float xo = xi * om;
    float denom = fmaf(d_k1 + d_k - 2.f * s_k, xo, s_k);
    float yv = fmaf(h_k, __fdividef(fmaf(s_k * xi, xi, d_k * xo), denom), y_k);
    float numer = s_k * s_k * fmaf(d_k1 * xi, xi, fmaf(2.f * s_k, xo, d_k * om * om));
    float ld = __logf(numer) - 2.f * __logf(denom);

    if (!(u >= -5.f && u <= 5.f)) { yv = u; ld = 0.f; }

    out[2 * i] = t;          // x_fix passthrough (FIX_DIM = 0)
    out[2 * i + 1] = yv;     // transformed x_var
    out[2 * BATCH + i] = ld; // log_det
}

extern "C" void kernel_launch(void* const* d_in, const int* in_sizes, int n_in,
                              void* d_out, int out_size) {
    const float* x  = (const float*)d_in[0];
    const float* W1 = (const float*)d_in[1];
    const float* b1 = (const float*)d_in[2];
    const float* W2 = (const float*)d_in[3];
    const float* b2 = (const float*)d_in[4];
    const float* W3 = (const float*)d_in[5];
    const float* b3 = (const float*)d_in[6];
    float* out = (float*)d_out;

    k_init<<<1, HID>>>(W1, b1);
    k_cross<<<HID + 1, HID>>>(W1, b1, W2, b2);
    k_rank<<<(CAP * 8 + 255) / 256, 256>>>();
    k_scatter<<<(CAP + 255) / 256, 256>>>();
    k_segcoef<<<(SEG_N + 7) / 8, 256>>>(W1, b1, W2, b2, W3, b3);
    k_main<<<BATCH / 256, 256>>>((const float2*)x, out);
}

// round 7
// speedup vs baseline: 1.8591x; 1.8591x over previous
#include <cuda_runtime.h>
#include <math.h>

#define BATCH 2097152
#define HID 64
#define NB 8
#define NRAW 25           // 3*NB + 1
#define CAP 4352          // raw breakpoint capacity (>= 64 + 65*64 = 4224)
#define SEG_N (CAP + 1)   // 4353 segments
#define SEG_STRIDE 52     // 25 (slope,intercept) pairs interleaved + 2 pad = 13 float4
#define GBUCK 4096        // grid buckets over [-8, 8], width 1/256
#define SEG_BLOCKS ((SEG_N + 7) / 8)   // 545 segment blocks in k_segcoef

// ---- scratch (static device globals; no allocation) ----
__device__ float g_theta_sorted[HID];
__device__ float g_bp_raw[CAP];
__device__ __align__(16) float g_bp_sorted[CAP + 8];
__device__ int   g_rank[CAP];
__device__ int   g_bp_count;
__device__ __align__(16) float g_seg[(size_t)SEG_N * SEG_STRIDE];
__device__ __align__(16) unsigned short g_grid[GBUCK + 8];
__device__ int   g_steps;

__device__ __forceinline__ float seg_eval_point(float lo, float hi) {
    bool lf = isfinite(lo), hf = isfinite(hi);
    if (lf && hf) return 0.5f * (lo + hi);
    if (lf) return lo + 1.0f;   // tail segment (lo, +inf)
    if (hf) return hi - 1.0f;   // tail segment (-inf, hi)
    return 0.0f;                // unreachable padding segment
}

// K1: init scratch, compute & sort layer-1 thresholds, seed breakpoint list
__global__ void k_init(const float* __restrict__ W1, const float* __restrict__ b1) {
    int i = threadIdx.x; // 256 threads
    for (int p = i; p < CAP; p += 256) { g_bp_raw[p] = INFINITY; g_rank[p] = 0; }
    if (i == 0) g_bp_count = 0;

    __shared__ float sth[HID];
    float th = INFINITY;
    if (i < HID) {
        float a = W1[i], b = b1[i];
        th = -b / a;
        if (!isfinite(th)) th = INFINITY; // a==0: constant unit; midpoint masks handle it
        sth[i] = th;
    }
    __syncthreads();
    if (i < HID) {
        int r = 0;
        for (int x = 0; x < HID; x++) {
            float u = sth[x];
            r += (u < th) || (u == th && x < i);
        }
        g_theta_sorted[r] = th;
        if (isfinite(th)) {
            int id = atomicAdd(&g_bp_count, 1);
            if (id < CAP) g_bp_raw[id] = th;
        }
    }
}

// K2: per layer-1 region, find layer-2 zero crossings, append as breakpoints
__global__ void k_cross(const float* __restrict__ W1, const float* __restrict__ b1,
                        const float* __restrict__ W2, const float* __restrict__ b2) {
    int idx = blockIdx.x * blockDim.x + threadIdx.x;
    if (idx >= (HID + 1) * HID) return;
    int j = idx & 63;       // layer-2 unit
    int r = idx >> 6;       // layer-1 region 0..64
    float lo = (r == 0)   ? -INFINITY : g_theta_sorted[r - 1];
    float hi = (r == HID) ?  INFINITY : g_theta_sorted[r];
    float t = seg_eval_point(lo, hi);

    float A = 0.f, Bc = __ldg(b2 + j);
    #pragma unroll 4
    for (int i = 0; i < HID; i++) {
        float a = __ldg(W1 + i), b = __ldg(b1 + i);
        float w = __ldg(W2 + j * HID + i);
        if (fmaf(a, t, b) > 0.f) { A = fmaf(w, a, A); Bc = fmaf(w, b, Bc); }
    }
    float tc = -Bc / A;
    if (isfinite(tc) && tc > lo && tc < hi) {
        int id = atomicAdd(&g_bp_count, 1);
        if (id < CAP) g_bp_raw[id] = tc;
    }
}

// K3a: rank-by-counting (32 slices per element)
__global__ void k_rank() {
    int idx = blockIdx.x * blockDim.x + threadIdx.x;
    if (idx >= CAP * 32) return;
    int g = idx >> 5, s = idx & 31;
    float v = g_bp_raw[g];
    int base = s * (CAP / 32);
    int part = 0;
    #pragma unroll 4
    for (int q = 0; q < CAP / 32; q++) {
        int x = base + q;
        float u = __ldg(g_bp_raw + x);
        part += ((u < v) || (u == v && x < g)) ? 1 : 0;
    }
    atomicAdd(&g_rank[g], part);
}

// K3b: scatter into sorted order (permutation; writes all CAP slots)
__global__ void k_scatter() {
    int g = blockIdx.x * blockDim.x + threadIdx.x;
    if (g < CAP) g_bp_sorted[g_rank[g]] = g_bp_raw[g];
}

// K4: per-segment exact affine coefficients of raw(t) (one warp per segment).
// Extra last block builds the bucket grid + uniform search step count.
__global__ void k_segcoef(const float* __restrict__ W1, const float* __restrict__ b1,
                          const float* __restrict__ W2, const float* __restrict__ b2,
                          const float* __restrict__ W3, const float* __restrict__ b3) {
    __shared__ float sW2[HID * 65];
    __shared__ float sW3[NRAW * HID];
    __shared__ float sa[HID], sb[HID];
    __shared__ unsigned short sg[GBUCK + 1];
    __shared__ int smax;
    int tid = threadIdx.x;

    if (blockIdx.x == SEG_BLOCKS) {
        // ---- grid builder block ----
        if (tid == 0) smax = 1;
        __syncthreads();
        for (int g = tid; g <= GBUCK; g += blockDim.x) {
            float edge = fmaf((float)g, 0.00390625f, -8.0f);
            int lo = 0, hi = CAP;
            while (lo < hi) {
                int mid = (lo + hi) >> 1;
                if (g_bp_sorted[mid] < edge) lo = mid + 1; else hi = mid;
            }
            sg[g] = (unsigned short)lo;
            g_grid[g] = (unsigned short)lo;
        }
        __syncthreads();
        int localmax = 1;
        for (int g = tid; g < GBUCK; g += blockDim.x) {
            int d;
            if (g == 0) d = (int)sg[1];                      // tail t < -8 span
            else if (g == GBUCK - 1) d = CAP - (int)sg[g];   // tail t >= 8 span
            else d = (int)sg[g + 1] - (int)sg[g];
            localmax = max(localmax, d);
        }
        atomicMax(&smax, localmax);
        __syncthreads();
        if (tid == 0) g_steps = 32 - __clz(smax);
        return;
    }

    for (int p = tid; p < HID * HID; p += blockDim.x) {
        int j = p >> 6, i = p & 63;
        sW2[j * 65 + i] = W2[p];
    }
    for (int p = tid; p < NRAW * HID; p += blockDim.x) sW3[p] = W3[p];
    if (tid < HID) { sa[tid] = W1[tid]; sb[tid] = b1[tid]; }
    __syncthreads();

    int warp = tid >> 5, lane = tid & 31;
    int m = blockIdx.x * (blockDim.x >> 5) + warp;
    if (m >= SEG_N) return;

    float lo = (m == 0)   ? -INFINITY : g_bp_sorted[m - 1];
    float hi = (m == CAP) ?  INFINITY : g_bp_sorted[m];
    float tm = seg_eval_point(lo, hi);

    int j0 = lane, j1 = lane + 32;
    float A0 = 0.f, B0 = __ldg(b2 + j0);
    float A1 = 0.f, B1 = __ldg(b2 + j1);
    #pragma unroll 4
    for (int i = 0; i < HID; i++) {
        float a = sa[i], b = sb[i];
        float va = 0.f, vb = 0.f;
        if (fmaf(a, tm, b) > 0.f) { va = a; vb = b; }
        float w0 = sW2[j0 * 65 + i], w1 = sW2[j1 * 65 + i];
        A0 = fmaf(w0, va, A0); B0 = fmaf(w0, vb, B0);
        A1 = fmaf(w1, va, A1); B1 = fmaf(w1, vb, B1);
    }
    if (!(fmaf(A0, tm, B0) > 0.f)) { A0 = 0.f; B0 = 0.f; }
    if (!(fmaf(A1, tm, B1) > 0.f)) { A1 = 0.f; B1 = 0.f; }

    float* segp = g_seg + (size_t)m * SEG_STRIDE;
    #pragma unroll
    for (int k = 0; k < NRAW; k++) {
        float s = sW3[k * HID + j0] * A0 + sW3[k * HID + j1] * A1;
        float c = sW3[k * HID + j0] * B0 + sW3[k * HID + j1] * B1;
        #pragma unroll
        for (int o = 16; o > 0; o >>= 1) {
            s += __shfl_xor_sync(0xffffffffu, s, o);
            c += __shfl_xor_sync(0xffffffffu, c, o);
        }
        if (lane == 0) { segp[2 * k] = s; segp[2 * k + 1] = c + __ldg(b3 + k); }
    }
    if (lane == 0) { segp[50] = 0.f; segp[51] = 0.f; }
}

// K5: main per-row kernel: grid lookup + short bisect + 25 FMAs + RQS spline
__global__ void __launch_bounds__(256) k_main(const float2* __restrict__ x,
                                              float* __restrict__ out) {
    int i = blockIdx.x * blockDim.x + threadIdx.x;
    float2 xv = __ldg(x + i);
    float t = xv.x, u = xv.y;

    // bucket with exact boundary correction (edges are exact multiples of 1/256)
    float mf = fmaf(t, 256.f, 2048.f);
    mf = fminf(fmaxf(mf, 0.f), 4095.f);
    int gb = (int)mf;
    float e0 = (float)(gb - 2048) * 0.00390625f;
    float e1 = e0 + 0.00390625f;
    gb += (t >= e1) ? 1 : 0;
    gb -= (t < e0) ? 1 : 0;
    gb = min(max(gb, 0), GBUCK - 1);
    e0 = (float)(gb - 2048) * 0.00390625f;
    e1 = e0 + 0.00390625f;
    int lo = (t >= e0) ? (int)__ldg(g_grid + gb) : 0;
    int hi = (t < e1) ? (int)__ldg(g_grid + gb + 1) : CAP;

    int steps = g_steps;  // uniform across grid
    for (int s = 0; s < steps; s++) {
        int mid = (lo + hi) >> 1;
        float v = __ldg(g_bp_sorted + mid);
        bool act = (lo < hi);
        bool go = act && (v < t);
        lo = go ? mid + 1 : lo;
        hi = (act && !go) ? mid : hi;
    }
    // lo == segment index p

    const float4* seg4 = (const float4*)(g_seg + (size_t)lo * SEG_STRIDE);
    float raw[NRAW];
    #pragma unroll
    for (int q = 0; q < 12; q++) {
        float4 v = __ldg(seg4 + q);
        raw[2 * q]     = fmaf(v.x, t, v.y);
        raw[2 * q + 1] = fmaf(v.z, t, v.w);
    }
    { float4 v = __ldg(seg4 + 12); raw[24] = fmaf(v.x, t, v.y); }

    // softmax(widths)*10
    float wm = raw[0];
    #pragma unroll
    for (int k = 1; k < NB; k++) wm = fmaxf(wm, raw[k]);
    float ew[NB], sumw = 0.f;
    #pragma unroll
    for (int k = 0; k < NB; k++) { ew[k] = __expf(raw[k] - wm); sumw += ew[k]; }
    float scw = __fdividef(10.0f, sumw);

    // softmax(heights)*10
    float hm = raw[NB];
    #pragma unroll
    for (int k = 1; k < NB; k++) hm = fmaxf(hm, raw[NB + k]);
    float eh[NB], sumh = 0.f;
    #pragma unroll
    for (int k = 0; k < NB; k++) { eh[k] = __expf(raw[NB + k] - hm); sumh += eh[k]; }
    float sch = __fdividef(10.0f, sumh);

    // softplus(derivs) + 0.001
    float dv[NB + 1];
    #pragma unroll
    for (int k = 0; k < NB + 1; k++) {
        float z = raw[2 * NB + k];
        dv[k] = fmaxf(z, 0.f) + __logf(1.0f + __expf(-fabsf(z))) + 0.001f;
    }

    // streaming cumsum + bin select (last k with cw_k < u wins; k=0 default)
    float cw = -5.f, ch = -5.f;
    float w_k = 0.f, h_k = 0.f, x_k = 0.f, y_k = 0.f, d_k = 0.f, d_k1 = 0.f;
    #pragma unroll
    for (int k = 0; k < NB; k++) {
        float wk = ew[k] * scw;
        float hk = eh[k] * sch;
        bool pr = (k == 0) || (cw < u);
        w_k  = pr ? wk    : w_k;
        h_k  = pr ? hk    : h_k;
        x_k  = pr ? cw    : x_k;
        y_k  = pr ? ch    : y_k;
        d_k  = pr ? dv[k] : d_k;
        d_k1 = pr ? dv[k + 1] : d_k1;
        cw += wk; ch += hk;
    }

    float rw = __fdividef(1.f, w_k);
    float s_k = h_k * rw;
    float xi = fminf(fmaxf((u - x_k) * rw, 0.f), 1.f);
    float om = 1.f - xi;
    float xo = xi * om;
    float denom = fmaf(d_k1 + d_k - 2.f * s_k, xo, s_k);
    float rden = __fdividef(1.f, denom);
    float yv = fmaf(h_k * rden, fmaf(s_k * xi, xi, d_k * xo), y_k);
    float numer = s_k * s_k * fmaf(d_k1 * xi, xi, fmaf(2.f * s_k, xo, d_k * om * om));
    float ld = __logf(numer * rden * rden);

    if (!(u >= -5.f && u <= 5.f)) { yv = u; ld = 0.f; }

    ((float2*)out)[i] = make_float2(t, yv);   // y row: [x_fix, y_var]
    out[2 * (size_t)BATCH + i] = ld;          // log_det
}

extern "C" void kernel_launch(void* const* d_in, const int* in_sizes, int n_in,
                              void* d_out, int out_size) {
    const float* x  = (const float*)d_in[0];
    const float* W1 = (const float*)d_in[1];
    const float* b1 = (const float*)d_in[2];
    const float* W2 = (const float*)d_in[3];
    const float* b2 = (const float*)d_in[4];
    const float* W3 = (const float*)d_in[5];
    const float* b3 = (const float*)d_in[6];
    float* out = (float*)d_out;

    k_init<<<1, 256>>>(W1, b1);
    k_cross<<<((HID + 1) * HID + 255) / 256, 256>>>(W1, b1, W2, b2);
    k_rank<<<(CAP * 32 + 255) / 256, 256>>>();
    k_scatter<<<(CAP + 255) / 256, 256>>>();
    k_segcoef<<<SEG_BLOCKS + 1, 256>>>(W1, b1, W2, b2, W3, b3);
    k_main<<<BATCH / 256, 256>>>((const float2*)x, out);
}